// round 17
// baseline (speedup 1.0000x reference)
#include <cuda_runtime.h>
#include <cuda_bf16.h>
#include <math.h>
#include <stdint.h>

// Batched logm(SPD): degree-8 polynomial of Ahat, 3 matmuls. ONE matrix per
// CTA, 320 threads (10 warps = 10 upper 32x32 tiles), 2 CTAs/SM.
// R17: u = x^2 + c x + d  =>  f8 = s*M1*M2 + e0*I EXACTLY (scalar remainder):
//   P1: Y0 = A^2 ; Wa = Y0 + c*A + d*I              (A kept in units 0/1)
//   P2: Y1 = Wa*Wa ; M1 = Y1 + a1*A + a0*I -> units 0/1 (pre-barrier)
//       M2 = Y1 + b2*Wa + (b1-c*b2)*A + (b0-d*b2)*I   (regs -> units 2/3)
//       acc <- (e0/s) * I
//   P3: F = s*(M1*M2 + (e0/s) I)
// Host: 7-unknown Newton (numeric Jacobian) from the proven R15 secant init;
// falls back to the proven full-E kernel if not converged.
// PACKED upper-block storage (pitch 80B, conflict-free); lower-block operand
// reads via transposed ldmatrix addressing. mma.sync bf16, 2-way split
// operands, 3 cross products, fp32 accumulate. 6 barriers.

#define MN 128
#define BPITCH 80
#define SLOT_BYTES (32 * BPITCH)        // 2560
#define UNIT_BYTES (10 * SLOT_BYTES)    // 25600
#define SM_TOTAL (4 * UNIT_BYTES)       // 102400 (per CTA; 2 CTAs/SM)
#define PF 132                          // fp32 result pitch (fbuf overlays units)

struct Coeffs {
    float tscale, tshift;
    float cc, dd;             // Wa = Y0 + cc*A + dd*I
    float a1c, a0c;           // M1 = Y1 + a1c*A + a0c*I
    float m2wa, m2a, m2i;     // M2 = Y1 + m2wa*Wa + m2a*A + m2i*I
    float ewa, ea, ei;        // full-E fallback: E/s = ewa*Wa + ea*A + ei*I
    float eis;                // scalar remainder path: acc preload = eis*I
    float sc;                 // F = sc*(M1*M2 + preload)
};

__device__ __forceinline__ uint32_t smem_u32(const void* p) {
    uint32_t a;
    asm("{ .reg .u64 t; cvta.to.shared.u64 t, %1; cvt.u32.u64 %0, t; }"
        : "=r"(a) : "l"(p));
    return a;
}
__device__ __forceinline__ void ldm_x4(uint32_t* r, uint32_t addr) {
    asm volatile("ldmatrix.sync.aligned.m8n8.x4.shared.b16 {%0,%1,%2,%3}, [%4];"
                 : "=r"(r[0]), "=r"(r[1]), "=r"(r[2]), "=r"(r[3]) : "r"(addr));
}
__device__ __forceinline__ void ldm_x4_t(uint32_t* r, uint32_t addr) {
    asm volatile("ldmatrix.sync.aligned.m8n8.x4.trans.shared.b16 {%0,%1,%2,%3}, [%4];"
                 : "=r"(r[0]), "=r"(r[1]), "=r"(r[2]), "=r"(r[3]) : "r"(addr));
}
__device__ __forceinline__ void mma16816(float* d, const uint32_t* a, const uint32_t* b) {
    asm volatile("mma.sync.aligned.m16n8k16.row.col.f32.bf16.bf16.f32 "
                 "{%0,%1,%2,%3}, {%4,%5,%6,%7}, {%8,%9}, {%0,%1,%2,%3};"
                 : "+f"(d[0]), "+f"(d[1]), "+f"(d[2]), "+f"(d[3])
                 : "r"(a[0]), "r"(a[1]), "r"(a[2]), "r"(a[3]), "r"(b[0]), "r"(b[1]));
}

// Packed upper-block offset: block (bi,bj), bi<=bj, slot-major.
__device__ __forceinline__ uint32_t boff_u(int r, int c) {
    uint32_t bi = (uint32_t)r >> 5, bj = (uint32_t)c >> 5;
    uint32_t slot = bi * 4u + bj - ((bi * (bi + 1u)) >> 1);
    return slot * SLOT_BYTES + (uint32_t)(r & 31) * BPITCH + (uint32_t)(c & 31) * 2u;
}

// Fused read of a split pair: 2 LDS + shift/mask unpack (bf16->f32 == <<16).
__device__ __forceinline__ void rdf2(const char* smemc, uint32_t hi, uint32_t lo,
                                     uint32_t off, float& v0, float& v1) {
    uint32_t H = *(const uint32_t*)(smemc + hi + off);
    uint32_t L = *(const uint32_t*)(smemc + lo + off);
    v0 = __uint_as_float(H << 16) + __uint_as_float(L << 16);
    v1 = __uint_as_float(H & 0xFFFF0000u) + __uint_as_float(L & 0xFFFF0000u);
}

// Packed split write: 2x cvt.rn.bf16x2 + shift hi-extract (exact residual).
__device__ __forceinline__ void wsplit(char* smemc, uint32_t hi, uint32_t lo,
                                       uint32_t off, float t0, float t1) {
    uint32_t hp;
    asm("cvt.rn.bf16x2.f32 %0, %1, %2;" : "=r"(hp) : "f"(t1), "f"(t0));  // lo16=t0
    float h0f = __uint_as_float(hp << 16);
    float h1f = __uint_as_float(hp & 0xFFFF0000u);
    uint32_t lp;
    asm("cvt.rn.bf16x2.f32 %0, %1, %2;" : "=r"(lp) : "f"(t1 - h1f), "f"(t0 - h0f));
    *(uint32_t*)(smemc + hi + off) = hp;
    *(uint32_t*)(smemc + lo + off) = lp;
}

#define U(u) ((uint32_t)((u) * UNIT_BYTES))

// Full-tile matmul: D(32x32) += Aop * Bop over K=128 (acc NOT zeroed).
// Operands packed-upper symmetric; lower blocks read transposed.
__device__ __forceinline__ void mm_full(uint32_t sb,
        uint32_t aHI, uint32_t aLO, uint32_t bHI, uint32_t bLO,
        int ti, int tj, int colbase, int g, int lr, float acc[2][4][4])
{
    const int rbase = ti * 32;
#pragma unroll
    for (int kc = 0; kc < 8; kc++) {
        const int k0 = kc * 16;
        const int kb = kc >> 1;
        uint32_t aH[2][4], aL[2][4];
        if (kb >= ti) {   // block (ti, kb) stored: rows mi*16 apart
            uint32_t ad = boff_u(rbase + ((g & 1) << 3) + lr, k0 + ((g >> 1) << 3));
            ldm_x4(aH[0], sb + aHI + ad);
            ldm_x4(aL[0], sb + aLO + ad);
            ldm_x4(aH[1], sb + aHI + ad + 16 * BPITCH);
            ldm_x4(aL[1], sb + aLO + ad + 16 * BPITCH);
        } else {          // use (kb, ti) transposed: cols mi*16 apart (+32 B)
            uint32_t ad = boff_u(k0 + ((g >> 1) << 3) + lr, rbase + ((g & 1) << 3));
            ldm_x4_t(aH[0], sb + aHI + ad);
            ldm_x4_t(aL[0], sb + aLO + ad);
            ldm_x4_t(aH[1], sb + aHI + ad + 32);
            ldm_x4_t(aL[1], sb + aLO + ad + 32);
        }
#pragma unroll
        for (int p = 0; p < 2; p++) {
            const int cB = colbase + p * 16;
            uint32_t bh[4], bl[4];
            if (kb <= tj) {   // block (kb, tj) stored
                uint32_t ad = boff_u(k0 + ((g & 1) << 3) + lr, cB + ((g >> 1) << 3));
                ldm_x4_t(bh, sb + bHI + ad);
                ldm_x4_t(bl, sb + bLO + ad);
            } else {          // use (tj, kb) transposed
                uint32_t ad = boff_u(cB + ((g >> 1) << 3) + lr, k0 + ((g & 1) << 3));
                ldm_x4(bh, sb + bHI + ad);
                ldm_x4(bl, sb + bLO + ad);
            }
#pragma unroll
            for (int mi = 0; mi < 2; mi++) {
                mma16816(acc[mi][2 * p],     aH[mi], bh);
                mma16816(acc[mi][2 * p],     aH[mi], bl);
                mma16816(acc[mi][2 * p],     aL[mi], bh);
                mma16816(acc[mi][2 * p + 1], aH[mi], bh + 2);
                mma16816(acc[mi][2 * p + 1], aH[mi], bl + 2);
                mma16816(acc[mi][2 * p + 1], aL[mi], bh + 2);
            }
        }
    }
}

__device__ __forceinline__ void zero244(float M[2][4][4]) {
#pragma unroll
    for (int m = 0; m < 2; m++)
#pragma unroll
        for (int i = 0; i < 4; i++)
#pragma unroll
            for (int j = 0; j < 4; j++)
                M[m][i][j] = 0.0f;
}

extern __shared__ char smem[];

// FULL_E = 1: proven R16 path (E = ewa*Wa + ea*A + ei*I in regs).
// FULL_E = 0: scalar remainder path (acc preload = eis*I; no E regs).
template<int FULL_E>
__device__ __forceinline__ void logm_body(const float* __restrict__ in,
                                          float* __restrict__ out, const Coeffs& cf)
{
    const uint32_t sb = smem_u32(smem);
    const int tid = threadIdx.x;
    const int w = tid >> 5;        // 0..9 = tile index
    const int lane = tid & 31;

    const int ti = (int)((0x3221110000ULL >> (w * 4)) & 15);
    const int tj = (int)((0x3323213210ULL >> (w * 4)) & 15);
    const int colbase = tj * 32;
    const bool diag = (ti == tj);
    const int rbase = ti * 32;

    const int g = lane >> 3;
    const int lr = lane & 7;

    const float* gA = in + (size_t)blockIdx.x * MN * MN;
    float* gO = out + (size_t)blockIdx.x * MN * MN;

    // ---- Prologue: pack upper blocks of Ahat (hi/lo) -> units 0/1 ----
    for (int p = tid; p < 10 * 512; p += 320) {
        int slot = p >> 9;
        int inner = p & 511;
        int ri = inner >> 4;
        int cip = (inner & 15) << 1;
        int bi = (int)((0x3221110000ULL >> (slot * 4)) & 15);
        int bj = (int)((0x3323213210ULL >> (slot * 4)) & 15);
        int r = bi * 32 + ri, c = bj * 32 + cip;
        float2 v2 = *(const float2*)(gA + r * MN + c);
        float v0 = v2.x * cf.tscale - ((r == c) ? cf.tshift : 0.0f);
        float v1 = v2.y * cf.tscale - ((r == c + 1) ? cf.tshift : 0.0f);
        uint32_t off = (uint32_t)(slot * SLOT_BYTES + ri * BPITCH + cip * 2);
        wsplit(smem, U(0), U(1), off, v0, v1);
    }
    __syncthreads();  // S0

    float acc[2][4][4];
    float E[FULL_E ? 2 : 1][4][4];

    // ---- P1: Y0 = A*A ; Wa = Y0 + cc*A + dd*I -> units 2/3 (virgin) ----
    zero244(acc);
    mm_full(sb, U(0), U(1), U(0), U(1), ti, tj, colbase, g, lr, acc);
#pragma unroll
    for (int mi = 0; mi < 2; mi++)
#pragma unroll
        for (int ni = 0; ni < 4; ni++)
#pragma unroll
            for (int e = 0; e < 2; e++) {
                int row = rbase + mi * 16 + (lane >> 2) + e * 8;
                int colp = colbase + ni * 8 + (lane & 3) * 2;
                uint32_t off = boff_u(row, colp);
                float a0, a1;
                rdf2(smem, U(0), U(1), off, a0, a1);
                float i0 = (row == colp)     ? cf.dd : 0.0f;
                float i1 = (row == colp + 1) ? cf.dd : 0.0f;
                wsplit(smem, U(2), U(3), off,
                       acc[mi][ni][2 * e] + cf.cc * a0 + i0,
                       acc[mi][ni][2 * e + 1] + cf.cc * a1 + i1);
            }
    __syncthreads();  // S1: Wa visible (A untouched in 0/1)

    // ---- P2: Y1 = Wa*Wa ----
    zero244(acc);
    mm_full(sb, U(2), U(3), U(2), U(3), ti, tj, colbase, g, lr, acc);

    // epi2a (pre-barrier): M1 -> units 0/1 (safe: P2 MMA reads only 2/3;
    // cross-warp A reads own-position disjoint). M2 -> acc (regs).
#pragma unroll
    for (int mi = 0; mi < 2; mi++)
#pragma unroll
        for (int ni = 0; ni < 4; ni++)
#pragma unroll
            for (int e = 0; e < 2; e++) {
                int row = rbase + mi * 16 + (lane >> 2) + e * 8;
                int colp = colbase + ni * 8 + (lane & 3) * 2;
                uint32_t off = boff_u(row, colp);
                float i0 = (row == colp)     ? 1.0f : 0.0f;
                float i1 = (row == colp + 1) ? 1.0f : 0.0f;
                float av0, av1, wa0, wa1;
                rdf2(smem, U(0), U(1), off, av0, av1);
                rdf2(smem, U(2), U(3), off, wa0, wa1);
                float y10 = acc[mi][ni][2 * e], y11 = acc[mi][ni][2 * e + 1];
                wsplit(smem, U(0), U(1), off,
                       y10 + cf.a1c * av0 + cf.a0c * i0,
                       y11 + cf.a1c * av1 + cf.a0c * i1);
                acc[mi][ni][2 * e]     = y10 + cf.m2wa * wa0 + cf.m2a * av0 + cf.m2i * i0;
                acc[mi][ni][2 * e + 1] = y11 + cf.m2wa * wa1 + cf.m2a * av1 + cf.m2i * i1;
                if (FULL_E) {
                    E[mi][ni][2 * e]     = cf.ewa * wa0 + cf.ea * av0 + cf.ei * i0;
                    E[mi][ni][2 * e + 1] = cf.ewa * wa1 + cf.ea * av1 + cf.ei * i1;
                }
            }
    __syncthreads();  // S2: all P2 MMA reads of Wa done

    // epi2b: M2 (regs) -> units 2/3 ; acc <- remainder preload
#pragma unroll
    for (int mi = 0; mi < 2; mi++)
#pragma unroll
        for (int ni = 0; ni < 4; ni++)
#pragma unroll
            for (int e = 0; e < 2; e++) {
                int row = rbase + mi * 16 + (lane >> 2) + e * 8;
                int colp = colbase + ni * 8 + (lane & 3) * 2;
                wsplit(smem, U(2), U(3), boff_u(row, colp),
                       acc[mi][ni][2 * e], acc[mi][ni][2 * e + 1]);
                if (FULL_E) {
                    acc[mi][ni][2 * e]     = E[mi][ni][2 * e];
                    acc[mi][ni][2 * e + 1] = E[mi][ni][2 * e + 1];
                } else {
                    acc[mi][ni][2 * e]     = (row == colp)     ? cf.eis : 0.0f;
                    acc[mi][ni][2 * e + 1] = (row == colp + 1) ? cf.eis : 0.0f;
                }
            }
    __syncthreads();  // S3: M1, M2 visible

    // ---- P3: acc += M1*M2 ; F = sc*acc ----
    mm_full(sb, U(0), U(1), U(2), U(3), ti, tj, colbase, g, lr, acc);
    __syncthreads();  // S4: all P3 MMA reads done; units may be retired

    // ---- fbuf (fp32, with transpose mirror) overlays the units ----
    {
        float* fb = (float*)smem;  // 128*132*4 = 67584 <= 102400
#pragma unroll
        for (int mi = 0; mi < 2; mi++)
#pragma unroll
            for (int ni = 0; ni < 4; ni++)
#pragma unroll
                for (int e = 0; e < 2; e++) {
                    int row = rbase + mi * 16 + (lane >> 2) + e * 8;
                    int colp = colbase + ni * 8 + (lane & 3) * 2;
                    float t0 = cf.sc * acc[mi][ni][2 * e];
                    float t1 = cf.sc * acc[mi][ni][2 * e + 1];
                    fb[row * PF + colp]     = t0;
                    fb[row * PF + colp + 1] = t1;
                    if (!diag) {
                        fb[colp * PF + row]       = t0;
                        fb[(colp + 1) * PF + row] = t1;
                    }
                }
    }
    __syncthreads();  // S5

    // ---- Coalesced global store ----
    const float* fb = (const float*)smem;
    for (int idx = tid; idx < MN * MN; idx += 320) {
        int r = idx >> 7, c = idx & 127;
        gO[idx] = fb[r * PF + c];
    }
}

__global__ void __launch_bounds__(320, 2)
logm_r17_kernel(const float* __restrict__ in, float* __restrict__ out, Coeffs cf)
{
    logm_body<0>(in, out, cf);
}

__global__ void __launch_bounds__(320, 2)
logm_r16_fallback_kernel(const float* __restrict__ in, float* __restrict__ out, Coeffs cf)
{
    logm_body<1>(in, out, cf);
}

// ---------------- Host: coefficient solves ----------------

// R15 structure: u = x^2 + c x (d=0), a0=b0=S0/2, quadratic remainder.
static void residual_u(const double* m, double s, double c, double b2,
                       double S1, double S0, double a1, double* R)
{
    double M1[5] = { 0.5 * S0, a1, c * c, 2.0 * c, 1.0 };
    double M2[5] = { 0.5 * S0, S1 - a1, c * c + b2, 2.0 * c, 1.0 };
    double P[9];
    for (int k = 0; k < 9; k++) P[k] = 0.0;
    for (int i = 0; i < 5; i++)
        for (int j = 0; j < 5; j++)
            P[i + j] += M1[i] * M2[j];
    for (int k = 0; k < 9; k++) R[k] = m[k] - s * P[k];
}

// R17 structure: u = x^2 + c x + d, free a0/b0; unknowns v = {c,d,b2,a1,b1,a0,b0}.
static void residual_v(const double* m, double s, const double* v, double* R)
{
    double c = v[0], d = v[1], b2 = v[2], a1 = v[3], b1 = v[4], a0 = v[5], b0 = v[6];
    double M1[5] = { d * d + a0, 2.0 * c * d + a1, c * c + 2.0 * d, 2.0 * c, 1.0 };
    double M2[5] = { d * d + b0, 2.0 * c * d + b1, c * c + 2.0 * d + b2, 2.0 * c, 1.0 };
    double P[9];
    for (int k = 0; k < 9; k++) P[k] = 0.0;
    for (int i = 0; i < 5; i++)
        for (int j = 0; j < 5; j++)
            P[i + j] += M1[i] * M2[j];
    for (int k = 0; k < 9; k++) R[k] = m[k] - s * P[k];
}

static int solve7(double J[7][7], double* rhs)  // Gaussian elim, partial pivot
{
    for (int col = 0; col < 7; col++) {
        int piv = col;
        for (int r = col + 1; r < 7; r++)
            if (fabs(J[r][col]) > fabs(J[piv][col])) piv = r;
        if (fabs(J[piv][col]) < 1e-14) return 0;
        if (piv != col) {
            for (int k = 0; k < 7; k++) { double t = J[col][k]; J[col][k] = J[piv][k]; J[piv][k] = t; }
            double t = rhs[col]; rhs[col] = rhs[piv]; rhs[piv] = t;
        }
        for (int r = col + 1; r < 7; r++) {
            double f = J[r][col] / J[col][col];
            for (int k = col; k < 7; k++) J[r][k] -= f * J[col][k];
            rhs[r] -= f * rhs[col];
        }
    }
    for (int r = 6; r >= 0; r--) {
        for (int k = r + 1; k < 7; k++) rhs[r] -= J[r][k] * rhs[k];
        rhs[r] /= J[r][r];
    }
    return 1;
}

static int compute_coeffs(Coeffs& cf)   // returns 1 if scalar-remainder path valid
{
    // Degree-8 Chebyshev fit of log(x) on [a,b]; spectrum in [1, ~5.6].
    const double a = 0.99, b = 6.00;
    const int MQ = 512;
    double d8[9];
    for (int k = 0; k < 9; k++) d8[k] = 0.0;
    for (int j = 0; j < MQ; j++) {
        double th = M_PI * (j + 0.5) / MQ;
        double x = 0.5 * (a + b) + 0.5 * (b - a) * cos(th);
        double f = log(x);
        for (int k = 0; k < 9; k++)
            d8[k] += f * cos(k * th);
    }
    for (int k = 0; k < 9; k++) d8[k] *= 2.0 / MQ;
    d8[0] *= 0.5;

    // Chebyshev -> monomial coefficients m[0..8]
    double m[9], Tkm1[9], Tk[9], Tn[9];
    for (int k = 0; k < 9; k++) { m[k] = 0.0; Tkm1[k] = 0.0; Tk[k] = 0.0; }
    Tkm1[0] = 1.0;
    Tk[1] = 1.0;
    for (int k = 0; k < 9; k++) m[k] += d8[0] * Tkm1[k] + d8[1] * Tk[k];
    for (int kk = 2; kk <= 8; kk++) {
        for (int k = 0; k < 9; k++) Tn[k] = -Tkm1[k];
        for (int k = 1; k < 9; k++) Tn[k] += 2.0 * Tk[k - 1];
        for (int k = 0; k < 9; k++) { m[k] += d8[kk] * Tn[k]; Tkm1[k] = Tk[k]; Tk[k] = Tn[k]; }
    }

    double s = m[8];

    // --- Stage 1: proven R15 secant cascade (init + fallback coefficients) ---
    double c15 = 0.0, b215 = 0.0, S1 = 0.0, S0 = 0.0, a115 = 0.0;
    {
        double* vars[5] = { &c15, &b215, &S1, &S0, &a115 };
        int ks[5] = { 7, 6, 5, 4, 3 };
        double R[9];
        for (int i = 0; i < 5; i++) {
            *vars[i] = 0.0;
            residual_u(m, s, c15, b215, S1, S0, a115, R);
            double r0 = R[ks[i]];
            *vars[i] = 1.0;
            residual_u(m, s, c15, b215, S1, S0, a115, R);
            double r1 = R[ks[i]];
            *vars[i] = -r0 / (r1 - r0);
        }
    }
    double R15[9];
    residual_u(m, s, c15, b215, S1, S0, a115, R15);

    cf.tscale = (float)(2.0 / (b - a));
    cf.tshift = (float)((a + b) / (b - a));
    cf.sc     = (float)s;

    // --- Stage 2: Newton for the scalar-remainder factorization ---
    double v[7] = { c15, 0.0, b215, a115, S1 - a115, 0.5 * S0, 0.5 * S0 };
    double R[9];
    int ok = 0;
    for (int it = 0; it < 60; it++) {
        residual_v(m, s, v, R);
        double nrm = 0.0;
        for (int k = 1; k <= 7; k++) nrm = fmax(nrm, fabs(R[k]));
        if (nrm < 1e-11) { ok = 1; break; }
        double J[7][7], rhs[7];
        for (int k = 0; k < 7; k++) rhs[k] = -R[k + 1];
        for (int j = 0; j < 7; j++) {
            double h = 1e-7 * fmax(1.0, fabs(v[j]));
            double vs = v[j];
            v[j] = vs + h;
            double Rp[9];
            residual_v(m, s, v, Rp);
            v[j] = vs;
            for (int k = 0; k < 7; k++) J[k][j] = (Rp[k + 1] - R[k + 1]) / h;
        }
        if (!solve7(J, rhs)) break;
        double step = 0.0;
        for (int k = 0; k < 7; k++) { v[k] += rhs[k]; step = fmax(step, fabs(rhs[k])); }
        if (step < 1e-14) { residual_v(m, s, v, R);
            double n2 = 0.0;
            for (int k = 1; k <= 7; k++) n2 = fmax(n2, fabs(R[k]));
            ok = (n2 < 1e-9); break; }
    }
    if (ok) {
        residual_v(m, s, v, R);
        double c = v[0], dd = v[1], b2 = v[2], a1 = v[3], b1 = v[4], a0 = v[5], b0 = v[6];
        cf.cc   = (float)c;
        cf.dd   = (float)dd;
        cf.a1c  = (float)a1;
        cf.a0c  = (float)a0;
        cf.m2wa = (float)b2;
        cf.m2a  = (float)(b1 - c * b2);
        cf.m2i  = (float)(b0 - dd * b2);
        cf.ewa = cf.ea = cf.ei = 0.0f;
        cf.eis  = (float)(R[0] / s);
        return 1;
    }
    // Fallback: proven R15/R16 coefficients (full E path, d=0)
    cf.cc   = (float)c15;
    cf.dd   = 0.0f;
    cf.a1c  = (float)a115;
    cf.a0c  = (float)(0.5 * S0);
    cf.m2wa = (float)b215;
    cf.m2a  = (float)((S1 - a115) - c15 * b215);
    cf.m2i  = (float)(0.5 * S0);
    cf.ewa  = (float)(R15[2] / s);
    cf.ea   = (float)((R15[1] - c15 * R15[2]) / s);
    cf.ei   = (float)(R15[0] / s);
    cf.eis  = 0.0f;
    return 0;
}

extern "C" void kernel_launch(void* const* d_in, const int* in_sizes, int n_in,
                              void* d_out, int out_size)
{
    const float* in = (const float*)d_in[0];
    float* out = (float*)d_out;
    int nmat = in_sizes[0] / (MN * MN);

    Coeffs cf;
    int scalar_rem = compute_coeffs(cf);

    cudaFuncSetAttribute(logm_r17_kernel,
                         cudaFuncAttributeMaxDynamicSharedMemorySize, SM_TOTAL);
    cudaFuncSetAttribute(logm_r16_fallback_kernel,
                         cudaFuncAttributeMaxDynamicSharedMemorySize, SM_TOTAL);

    if (scalar_rem)
        logm_r17_kernel<<<nmat, 320, SM_TOTAL>>>(in, out, cf);
    else
        logm_r16_fallback_kernel<<<nmat, 320, SM_TOTAL>>>(in, out, cf);
}